// round 5
// baseline (speedup 1.0000x reference)
#include <cuda_runtime.h>
#include <cstddef>

#define BB 16384
#define GG 128
#define SS 64
#define HH 10
#define PHH 100

// 8MB scratch for gene_layer, stored TRANSPOSED: glT[g][b]
__device__ float g_glT[GG * BB];

// packed fp32x2 FMA (Blackwell; inline PTX only)
__device__ __forceinline__ unsigned long long f2fma(unsigned long long a,
                                                    unsigned long long b,
                                                    unsigned long long c) {
    unsigned long long d;
    asm("fma.rn.f32x2 %0, %1, %2, %3;" : "=l"(d) : "l"(a), "l"(b), "l"(c));
    return d;
}
__device__ __forceinline__ float f2lo(unsigned long long a) {
    return __uint_as_float((unsigned)a);
}
__device__ __forceinline__ float f2hi(unsigned long long a) {
    return __uint_as_float((unsigned)(a >> 32));
}
__device__ __forceinline__ unsigned long long f2dup(float v) {
    unsigned long long d;
    asm("mov.b64 %0, {%1, %1};" : "=l"(d) : "f"(v));
    return d;
}

extern __shared__ unsigned char dynsmem[];

// ---------------------------------------------------------------------------
// Kernel A: gene_layer[b,g] = W2 . relu(x[b,g,:] @ W1[g] + b1) + b2
// Block = (gene, 512-row tile), 128 threads (4 warps -> all 4 SMSPs),
// R=4 rows/thread. Crossbar/32rows = 64(STS)+64(x)+160(W) = 288 cyc.
// ---------------------------------------------------------------------------
#define AR 512      // rows per block
#define ATH 128     // threads (NEVER 64: wid%4 SMSP mapping)
#define XPAD 68     // floats per smem row: LDS.128 8-lane phases conflict-free

#define A_SMEM_FLOATS (AR * XPAD + HH * SS + 36)
#define A_SMEM_BYTES (A_SMEM_FLOATS * 4)

__global__ void __launch_bounds__(ATH, 1)
kernelA(const float* __restrict__ x, const float* __restrict__ W1,
        const float* __restrict__ b1, const float* __restrict__ W2,
        const float* __restrict__ b2) {
    float* xs  = (float*)dynsmem;        // [AR][XPAD]
    float* wt  = xs + AR * XPAD;         // [HH][SS]  wt[h][s]
    float* sb1 = wt + HH * SS;           // [16]
    float* sW2 = sb1 + 16;               // [16]
    float* sb2 = sW2 + 16;               // [1]

    const int tid = threadIdx.x;
    const int g = blockIdx.x;
    const int b0 = blockIdx.y * AR;

    // stage W1[g] transposed (tiny)
    {
        const float* W1g = W1 + (size_t)g * (SS * HH);
        for (int i = tid; i < SS * HH; i += ATH) {
            int s = i / HH, h = i - s * HH;
            wt[h * SS + s] = W1g[i];
        }
        if (tid < HH) {
            sb1[tid] = b1[g * HH + tid];
            sW2[tid] = W2[g * HH + tid];
        }
        if (tid == 0) sb2[0] = b2[g];
    }

    // stage x tile coalesced: xs[r][0..63] = x[b0+r, g, :]
    // 16 lanes cover one 256B row contiguously; high MLP via unroll
#pragma unroll 8
    for (int i = tid; i < AR * 16; i += ATH) {
        int r = i >> 4, q = i & 15;
        float4 v = *(const float4*)(x + (((size_t)(b0 + r)) * GG + g) * SS + 4 * q);
        *(float4*)(xs + r * XPAD + 4 * q) = v;
    }
    __syncthreads();

    // compute: rows tid+128k (k=0..3); q outer, h inner; 40 f32x2 accums
    unsigned long long a0[HH], a1[HH], a2[HH], a3[HH];
#pragma unroll
    for (int h = 0; h < HH; h++) { a0[h] = 0ull; a1[h] = 0ull; a2[h] = 0ull; a3[h] = 0ull; }

#pragma unroll 4
    for (int q = 0; q < 16; q++) {
        ulonglong2 xa = *(const ulonglong2*)(xs + (tid)       * XPAD + 4 * q);
        ulonglong2 xb = *(const ulonglong2*)(xs + (tid + 128) * XPAD + 4 * q);
        ulonglong2 xc = *(const ulonglong2*)(xs + (tid + 256) * XPAD + 4 * q);
        ulonglong2 xd = *(const ulonglong2*)(xs + (tid + 384) * XPAD + 4 * q);
#pragma unroll
        for (int h = 0; h < HH; h++) {
            ulonglong2 w = *(const ulonglong2*)(wt + h * SS + 4 * q);  // broadcast
            a0[h] = f2fma(xa.x, w.x, a0[h]);
            a1[h] = f2fma(xb.x, w.x, a1[h]);
            a2[h] = f2fma(xc.x, w.x, a2[h]);
            a3[h] = f2fma(xd.x, w.x, a3[h]);
            a0[h] = f2fma(xa.y, w.y, a0[h]);
            a1[h] = f2fma(xb.y, w.y, a1[h]);
            a2[h] = f2fma(xc.y, w.y, a2[h]);
            a3[h] = f2fma(xd.y, w.y, a3[h]);
        }
    }

    // epilogue: relu + H->1 projection, coalesced store
    float o0 = sb2[0], o1 = sb2[0], o2 = sb2[0], o3 = sb2[0];
#pragma unroll
    for (int h = 0; h < HH; h++) {
        float v0 = f2lo(a0[h]) + f2hi(a0[h]) + sb1[h];
        float v1 = f2lo(a1[h]) + f2hi(a1[h]) + sb1[h];
        float v2 = f2lo(a2[h]) + f2hi(a2[h]) + sb1[h];
        float v3 = f2lo(a3[h]) + f2hi(a3[h]) + sb1[h];
        o0 = fmaf(fmaxf(v0, 0.f), sW2[h], o0);
        o1 = fmaf(fmaxf(v1, 0.f), sW2[h], o1);
        o2 = fmaf(fmaxf(v2, 0.f), sW2[h], o2);
        o3 = fmaf(fmaxf(v3, 0.f), sW2[h], o3);
    }
    float* glrow = g_glT + (size_t)g * BB + b0;
    glrow[tid]       = o0;
    glrow[tid + 128] = o1;
    glrow[tid + 256] = o2;
    glrow[tid + 384] = o3;
}

// ---------------------------------------------------------------------------
// Kernel B: out[b] = relu(gl[b,:] @ Wp1 + bp1) @ Wp2 + bp2
// 128 blocks x 256 threads. Block = 128 rows x 128 j (PH padded to 128).
// Thread = (rowslot 0..31 -> rows r,+32,+64,+96) x (jsub 0..7 -> 16 j).
// ---------------------------------------------------------------------------
#define B_THREADS 256
#define B_ROWSB 128
#define PHP 128
#define B_SMEM_FLOATS (GG * B_ROWSB + GG * PHP + PHP + PHP + 8 * B_ROWSB)
#define B_SMEM_BYTES (B_SMEM_FLOATS * 4)

__global__ void __launch_bounds__(B_THREADS, 1)
kernelB(const float* __restrict__ Wp1, const float* __restrict__ bp1,
        const float* __restrict__ Wp2, const float* __restrict__ bp2,
        float* __restrict__ out) {
    float* gls  = (float*)dynsmem;            // [G][128] (g-major)
    float* sWp1 = gls + GG * B_ROWSB;         // [G][128] zero-padded
    float* sbp1 = sWp1 + GG * PHP;            // [128]
    float* sWp2 = sbp1 + PHP;                 // [128]
    float* op   = sWp2 + PHP;                 // [8][128] partials

    const int tid = threadIdx.x;
    const int b0 = blockIdx.x * B_ROWSB;

    // stage gene_layer tile (vectorized, coalesced from transposed scratch)
#pragma unroll 4
    for (int i = tid; i < GG * (B_ROWSB / 4); i += B_THREADS) {
        int k = i & 31, g = i >> 5;   // 32 float4 per gene row
        *(float4*)(gls + g * B_ROWSB + 4 * k) =
            *(const float4*)(g_glT + (size_t)g * BB + b0 + 4 * k);
    }
#pragma unroll 4
    for (int i = tid; i < GG * PHP; i += B_THREADS) {
        int g = i >> 7, j = i & (PHP - 1);
        sWp1[i] = (j < PHH) ? Wp1[g * PHH + j] : 0.f;
    }
    if (tid < PHP) {
        sbp1[tid] = (tid < PHH) ? bp1[tid] : 0.f;
        sWp2[tid] = (tid < PHH) ? Wp2[tid] : 0.f;
    }
    __syncthreads();

    const int row  = tid & 31;        // rows: row + 32k
    const int jsub = tid >> 5;        // warp-uniform: 8 subsets x 16 j
    const int jb   = jsub * 16;

    unsigned long long acc[4][8];
#pragma unroll
    for (int k = 0; k < 4; k++)
#pragma unroll
        for (int c = 0; c < 8; c++) acc[k][c] = 0ull;

#pragma unroll 2
    for (int g = 0; g < GG; g++) {
        const float* gr = gls + g * B_ROWSB + row;
        unsigned long long x0 = f2dup(gr[0]);
        unsigned long long x1 = f2dup(gr[32]);
        unsigned long long x2 = f2dup(gr[64]);
        unsigned long long x3 = f2dup(gr[96]);
        const ulonglong2* wp = (const ulonglong2*)(sWp1 + g * PHP + jb);
#pragma unroll
        for (int p = 0; p < 4; p++) {
            ulonglong2 w = wp[p];
            acc[0][2 * p]     = f2fma(x0, w.x, acc[0][2 * p]);
            acc[1][2 * p]     = f2fma(x1, w.x, acc[1][2 * p]);
            acc[2][2 * p]     = f2fma(x2, w.x, acc[2][2 * p]);
            acc[3][2 * p]     = f2fma(x3, w.x, acc[3][2 * p]);
            acc[0][2 * p + 1] = f2fma(x0, w.y, acc[0][2 * p + 1]);
            acc[1][2 * p + 1] = f2fma(x1, w.y, acc[1][2 * p + 1]);
            acc[2][2 * p + 1] = f2fma(x2, w.y, acc[2][2 * p + 1]);
            acc[3][2 * p + 1] = f2fma(x3, w.y, acc[3][2 * p + 1]);
        }
    }

#pragma unroll
    for (int k = 0; k < 4; k++) {
        float o = 0.f;
#pragma unroll
        for (int c = 0; c < 8; c++) {
            int j0 = jb + 2 * c, j1 = j0 + 1;
            float p0 = fmaxf(f2lo(acc[k][c]) + sbp1[j0], 0.f);
            float p1 = fmaxf(f2hi(acc[k][c]) + sbp1[j1], 0.f);
            o = fmaf(p0, sWp2[j0], o);
            o = fmaf(p1, sWp2[j1], o);
        }
        op[jsub * B_ROWSB + row + 32 * k] = o;
    }
    __syncthreads();

    if (tid < B_ROWSB) {
        float v = bp2[0];
#pragma unroll
        for (int c = 0; c < 8; c++) v += op[c * B_ROWSB + tid];
        out[b0 + tid] = v;
    }
}

// ---------------------------------------------------------------------------
extern "C" void kernel_launch(void* const* d_in, const int* in_sizes, int n_in,
                              void* d_out, int out_size) {
    const float* x   = (const float*)d_in[0];
    const float* W1  = (const float*)d_in[1];
    const float* b1  = (const float*)d_in[2];
    const float* W2  = (const float*)d_in[3];
    const float* b2  = (const float*)d_in[4];
    const float* Wp1 = (const float*)d_in[5];
    const float* bp1 = (const float*)d_in[6];
    const float* Wp2 = (const float*)d_in[7];
    const float* bp2 = (const float*)d_in[8];
    float* out = (float*)d_out;

    cudaFuncSetAttribute(kernelA, cudaFuncAttributeMaxDynamicSharedMemorySize,
                         A_SMEM_BYTES);
    cudaFuncSetAttribute(kernelB, cudaFuncAttributeMaxDynamicSharedMemorySize,
                         B_SMEM_BYTES);

    dim3 gridA(GG, BB / AR);   // concurrent wave covers contiguous x slab
    kernelA<<<gridA, ATH, A_SMEM_BYTES>>>(x, W1, b1, W2, b2);

    dim3 gridB(BB / B_ROWSB);
    kernelB<<<gridB, B_THREADS, B_SMEM_BYTES>>>(Wp1, bp1, Wp2, bp2, out);
}

// round 7
// speedup vs baseline: 1.5135x; 1.5135x over previous
#include <cuda_runtime.h>
#include <cstddef>

#define BB 16384
#define GG 128
#define SS 64
#define HH 10
#define PHH 100

// 8MB scratch for gene_layer, stored TRANSPOSED: glT[g][b]
__device__ float g_glT[GG * BB];

// packed fp32x2 FMA (Blackwell; inline PTX only)
__device__ __forceinline__ unsigned long long f2fma(unsigned long long a,
                                                    unsigned long long b,
                                                    unsigned long long c) {
    unsigned long long d;
    asm("fma.rn.f32x2 %0, %1, %2, %3;" : "=l"(d) : "l"(a), "l"(b), "l"(c));
    return d;
}
__device__ __forceinline__ float f2lo(unsigned long long a) {
    return __uint_as_float((unsigned)a);
}
__device__ __forceinline__ float f2hi(unsigned long long a) {
    return __uint_as_float((unsigned)(a >> 32));
}
__device__ __forceinline__ unsigned long long f2dup(float v) {
    unsigned long long d;
    asm("mov.b64 %0, {%1, %1};" : "=l"(d) : "f"(v));
    return d;
}

extern __shared__ unsigned char dynsmem[];

// ---------------------------------------------------------------------------
// Kernel A: gene_layer[b,g] = W2 . relu(x[b,g,:] @ W1[g] + b1) + b2
// Block = (gene, 384-row tile), 128 threads (4 warps -> all SMSPs), R=3.
// smem ~107KB -> 2 blocks/SM so stage(n+1) overlaps compute(n).
// Crossbar/32rows = 64(STS)+64(x)+213(W/3) ~= 341 cyc.
// ---------------------------------------------------------------------------
#define AR 384        // rows per block (42 full tiles + 256-row tail)
#define ATH 128
#define XPAD 68       // floats/row: 16B-aligned pitch, conflict-free phases
#define NTILES 43     // ceil(16384/384)

#define A_SMEM_FLOATS (AR * XPAD + HH * SS + 36)
#define A_SMEM_BYTES (A_SMEM_FLOATS * 4)

__global__ void __launch_bounds__(ATH, 2)
kernelA(const float* __restrict__ x, const float* __restrict__ W1,
        const float* __restrict__ b1, const float* __restrict__ W2,
        const float* __restrict__ b2) {
    float* xs  = (float*)dynsmem;        // [AR][XPAD]
    float* wt  = xs + AR * XPAD;         // [HH][SS]  wt[h][s]
    float* sb1 = wt + HH * SS;           // [16]
    float* sW2 = sb1 + 16;               // [16]
    float* sb2 = sW2 + 16;               // [1]

    const int tid = threadIdx.x;
    const int g = blockIdx.x;
    const int b0 = blockIdx.y * AR;
    const int nrows = (BB - b0 < AR) ? (BB - b0) : AR;   // 384 or 256 (tail)

    // stage W1[g] transposed (tiny)
    {
        const float* W1g = W1 + (size_t)g * (SS * HH);
        for (int i = tid; i < SS * HH; i += ATH) {
            int s = i / HH, h = i - s * HH;
            wt[h * SS + s] = W1g[i];
        }
        if (tid < HH) {
            sb1[tid] = b1[g * HH + tid];
            sW2[tid] = W2[g * HH + tid];
        }
        if (tid == 0) sb2[0] = b2[g];
    }

    // stage x tile coalesced: xs[r][0..63] = x[b0+r, g, :]
#pragma unroll 8
    for (int i = tid; i < nrows * 16; i += ATH) {
        int r = i >> 4, q = i & 15;
        float4 v = *(const float4*)(x + (((size_t)(b0 + r)) * GG + g) * SS + 4 * q);
        *(float4*)(xs + r * XPAD + 4 * q) = v;
    }
    __syncthreads();

    // compute: rows tid, tid+128, tid+256; q outer, h inner; 30 f32x2 accums
    const bool v2 = (tid + 256) < nrows;           // only 3rd row needs guard
    const int r2 = v2 ? (tid + 256) : 0;           // clamp (store guarded)

    unsigned long long a0[HH], a1[HH], a2[HH];
#pragma unroll
    for (int h = 0; h < HH; h++) { a0[h] = 0ull; a1[h] = 0ull; a2[h] = 0ull; }

#pragma unroll 4
    for (int q = 0; q < 16; q++) {
        ulonglong2 xa = *(const ulonglong2*)(xs + (tid)       * XPAD + 4 * q);
        ulonglong2 xb = *(const ulonglong2*)(xs + (tid + 128) * XPAD + 4 * q);
        ulonglong2 xc = *(const ulonglong2*)(xs + r2          * XPAD + 4 * q);
#pragma unroll
        for (int h = 0; h < HH; h++) {
            ulonglong2 w = *(const ulonglong2*)(wt + h * SS + 4 * q);  // broadcast
            a0[h] = f2fma(xa.x, w.x, a0[h]);
            a1[h] = f2fma(xb.x, w.x, a1[h]);
            a2[h] = f2fma(xc.x, w.x, a2[h]);
            a0[h] = f2fma(xa.y, w.y, a0[h]);
            a1[h] = f2fma(xb.y, w.y, a1[h]);
            a2[h] = f2fma(xc.y, w.y, a2[h]);
        }
    }

    // epilogue: relu + H->1 projection, coalesced store
    float o0 = sb2[0], o1 = sb2[0], o2 = sb2[0];
#pragma unroll
    for (int h = 0; h < HH; h++) {
        float w2h = sW2[h];
        float v0 = f2lo(a0[h]) + f2hi(a0[h]) + sb1[h];
        float v1 = f2lo(a1[h]) + f2hi(a1[h]) + sb1[h];
        float vv2 = f2lo(a2[h]) + f2hi(a2[h]) + sb1[h];
        o0 = fmaf(fmaxf(v0, 0.f), w2h, o0);
        o1 = fmaf(fmaxf(v1, 0.f), w2h, o1);
        o2 = fmaf(fmaxf(vv2, 0.f), w2h, o2);
    }
    float* glrow = g_glT + (size_t)g * BB + b0;
    glrow[tid]       = o0;
    glrow[tid + 128] = o1;
    if (v2) glrow[tid + 256] = o2;
}

// ---------------------------------------------------------------------------
// Kernel B: out[b] = relu(gl[b,:] @ Wp1 + bp1) @ Wp2 + bp2
// 128 blocks x 256 threads. Block = 128 rows x 128 j (PH padded to 128).
// Thread = (rowslot 0..31 -> rows r,+32,+64,+96) x (jsub 0..7 -> 16 j).
// ---------------------------------------------------------------------------
#define B_THREADS 256
#define B_ROWSB 128
#define PHP 128
#define B_SMEM_FLOATS (GG * B_ROWSB + GG * PHP + PHP + PHP + 8 * B_ROWSB)
#define B_SMEM_BYTES (B_SMEM_FLOATS * 4)

__global__ void __launch_bounds__(B_THREADS, 1)
kernelB(const float* __restrict__ Wp1, const float* __restrict__ bp1,
        const float* __restrict__ Wp2, const float* __restrict__ bp2,
        float* __restrict__ out) {
    float* gls  = (float*)dynsmem;            // [G][128] (g-major)
    float* sWp1 = gls + GG * B_ROWSB;         // [G][128] zero-padded
    float* sbp1 = sWp1 + GG * PHP;            // [128]
    float* sWp2 = sbp1 + PHP;                 // [128]
    float* op   = sWp2 + PHP;                 // [8][128] partials

    const int tid = threadIdx.x;
    const int b0 = blockIdx.x * B_ROWSB;

    // stage gene_layer tile (vectorized, coalesced from transposed scratch)
#pragma unroll 4
    for (int i = tid; i < GG * (B_ROWSB / 4); i += B_THREADS) {
        int k = i & 31, g = i >> 5;   // 32 float4 per gene row
        *(float4*)(gls + g * B_ROWSB + 4 * k) =
            *(const float4*)(g_glT + (size_t)g * BB + b0 + 4 * k);
    }
#pragma unroll 4
    for (int i = tid; i < GG * PHP; i += B_THREADS) {
        int g = i >> 7, j = i & (PHP - 1);
        sWp1[i] = (j < PHH) ? Wp1[g * PHH + j] : 0.f;
    }
    if (tid < PHP) {
        sbp1[tid] = (tid < PHH) ? bp1[tid] : 0.f;
        sWp2[tid] = (tid < PHH) ? Wp2[tid] : 0.f;
    }
    __syncthreads();

    const int row  = tid & 31;        // rows: row + 32k
    const int jsub = tid >> 5;        // warp-uniform: 8 subsets x 16 j
    const int jb   = jsub * 16;

    unsigned long long acc[4][8];
#pragma unroll
    for (int k = 0; k < 4; k++)
#pragma unroll
        for (int c = 0; c < 8; c++) acc[k][c] = 0ull;

#pragma unroll 2
    for (int g = 0; g < GG; g++) {
        const float* gr = gls + g * B_ROWSB + row;
        unsigned long long x0 = f2dup(gr[0]);
        unsigned long long x1 = f2dup(gr[32]);
        unsigned long long x2 = f2dup(gr[64]);
        unsigned long long x3 = f2dup(gr[96]);
        const ulonglong2* wp = (const ulonglong2*)(sWp1 + g * PHP + jb);
#pragma unroll
        for (int p = 0; p < 4; p++) {
            ulonglong2 w = wp[p];
            acc[0][2 * p]     = f2fma(x0, w.x, acc[0][2 * p]);
            acc[1][2 * p]     = f2fma(x1, w.x, acc[1][2 * p]);
            acc[2][2 * p]     = f2fma(x2, w.x, acc[2][2 * p]);
            acc[3][2 * p]     = f2fma(x3, w.x, acc[3][2 * p]);
            acc[0][2 * p + 1] = f2fma(x0, w.y, acc[0][2 * p + 1]);
            acc[1][2 * p + 1] = f2fma(x1, w.y, acc[1][2 * p + 1]);
            acc[2][2 * p + 1] = f2fma(x2, w.y, acc[2][2 * p + 1]);
            acc[3][2 * p + 1] = f2fma(x3, w.y, acc[3][2 * p + 1]);
        }
    }

#pragma unroll
    for (int k = 0; k < 4; k++) {
        float o = 0.f;
#pragma unroll
        for (int c = 0; c < 8; c++) {
            int j0 = jb + 2 * c, j1 = j0 + 1;
            float p0 = fmaxf(f2lo(acc[k][c]) + sbp1[j0], 0.f);
            float p1 = fmaxf(f2hi(acc[k][c]) + sbp1[j1], 0.f);
            o = fmaf(p0, sWp2[j0], o);
            o = fmaf(p1, sWp2[j1], o);
        }
        op[jsub * B_ROWSB + row + 32 * k] = o;
    }
    __syncthreads();

    if (tid < B_ROWSB) {
        float v = bp2[0];
#pragma unroll
        for (int c = 0; c < 8; c++) v += op[c * B_ROWSB + tid];
        out[b0 + tid] = v;
    }
}

// ---------------------------------------------------------------------------
extern "C" void kernel_launch(void* const* d_in, const int* in_sizes, int n_in,
                              void* d_out, int out_size) {
    const float* x   = (const float*)d_in[0];
    const float* W1  = (const float*)d_in[1];
    const float* b1  = (const float*)d_in[2];
    const float* W2  = (const float*)d_in[3];
    const float* b2  = (const float*)d_in[4];
    const float* Wp1 = (const float*)d_in[5];
    const float* bp1 = (const float*)d_in[6];
    const float* Wp2 = (const float*)d_in[7];
    const float* bp2 = (const float*)d_in[8];
    float* out = (float*)d_out;

    cudaFuncSetAttribute(kernelA, cudaFuncAttributeMaxDynamicSharedMemorySize,
                         A_SMEM_BYTES);
    cudaFuncSetAttribute(kernelB, cudaFuncAttributeMaxDynamicSharedMemorySize,
                         B_SMEM_BYTES);

    dim3 gridA(GG, NTILES);   // concurrent wave covers contiguous x slab
    kernelA<<<gridA, ATH, A_SMEM_BYTES>>>(x, W1, b1, W2, b2);

    dim3 gridB(BB / B_ROWSB);
    kernelB<<<gridB, B_THREADS, B_SMEM_BYTES>>>(Wp1, bp1, Wp2, bp2, out);
}

// round 8
// speedup vs baseline: 1.5590x; 1.0301x over previous
#include <cuda_runtime.h>
#include <cstddef>
#include <cstdint>

#define BB 16384
#define GG 128
#define SS 64
#define HH 10
#define PHH 100

// 8MB scratch for gene_layer, stored TRANSPOSED: glT[g][b]
__device__ float g_glT[GG * BB];

// packed fp32x2 FMA (Blackwell; inline PTX only)
__device__ __forceinline__ unsigned long long f2fma(unsigned long long a,
                                                    unsigned long long b,
                                                    unsigned long long c) {
    unsigned long long d;
    asm("fma.rn.f32x2 %0, %1, %2, %3;" : "=l"(d) : "l"(a), "l"(b), "l"(c));
    return d;
}
__device__ __forceinline__ float f2lo(unsigned long long a) {
    return __uint_as_float((unsigned)a);
}
__device__ __forceinline__ float f2hi(unsigned long long a) {
    return __uint_as_float((unsigned)(a >> 32));
}
__device__ __forceinline__ unsigned long long f2dup(float v) {
    unsigned long long d;
    asm("mov.b64 %0, {%1, %1};" : "=l"(d) : "f"(v));
    return d;
}
__device__ __forceinline__ uint32_t smem_u32(const void* p) {
    uint32_t a;
    asm("{ .reg .u64 t; cvta.to.shared.u64 t, %1; cvt.u32.u64 %0, t; }"
        : "=r"(a) : "l"(p));
    return a;
}
__device__ __forceinline__ void cpasync16(uint32_t dst, const void* src) {
    asm volatile("cp.async.cg.shared.global [%0], [%1], 16;"
                 :: "r"(dst), "l"(src));
}
#define CP_COMMIT() asm volatile("cp.async.commit_group;" ::: "memory")
#define CP_WAIT(n)  asm volatile("cp.async.wait_group %0;" :: "n"(n) : "memory")

extern __shared__ unsigned char dynsmem[];

// ---------------------------------------------------------------------------
// Kernel A: gene_layer[b,g] = W2 . relu(x[b,g,:] @ W1[g] + b1) + b2
// Block = (gene, 368-row tile), 128 threads, R=3 rows/thread.
// x staged in TWO 32-column s-halves via cp.async double buffering:
// compute(half0) overlaps DRAM fetch of half1. 2 blocks/SM.
// ---------------------------------------------------------------------------
#define AR 368        // rows per block
#define ATH 128
#define HPAD 36       // floats per row per s-half (32 + 4): 16B pitch, no conflicts
#define NT 45         // ceil(16384/368)

#define A_SMEM_FLOATS (2 * AR * HPAD + HH * SS + 36)
#define A_SMEM_BYTES (A_SMEM_FLOATS * 4)

__global__ void __launch_bounds__(ATH, 2)
kernelA(const float* __restrict__ x, const float* __restrict__ W1,
        const float* __restrict__ b1, const float* __restrict__ W2,
        const float* __restrict__ b2, int tile_off) {
    float* xh0 = (float*)dynsmem;        // [AR][HPAD] s in [0,32)
    float* xh1 = xh0 + AR * HPAD;        // [AR][HPAD] s in [32,64)
    float* wt  = xh1 + AR * HPAD;        // [HH][SS]  wt[h][s]
    float* sb1 = wt + HH * SS;           // [16]
    float* sW2 = sb1 + 16;               // [16]
    float* sb2 = sW2 + 16;               // [1]

    const int tid = threadIdx.x;
    const int g = blockIdx.x;
    const int tile = blockIdx.y + tile_off;
    const int b0 = tile * AR;
    const int nrows = (BB - b0 < AR) ? (BB - b0) : AR;

    const uint32_t xh0a = smem_u32(xh0);
    const uint32_t xh1a = smem_u32(xh1);

    // issue cp.async stages for both halves (grouped per half)
    {
        const float* xg = x + ((size_t)b0 * GG + g) * SS;
#pragma unroll 4
        for (int i = tid; i < nrows * 8; i += ATH) {
            int r = i >> 3, c = i & 7;
            cpasync16(xh0a + (r * HPAD + 4 * c) * 4,
                      xg + (size_t)r * (GG * SS) + 4 * c);
        }
        CP_COMMIT();
#pragma unroll 4
        for (int i = tid; i < nrows * 8; i += ATH) {
            int r = i >> 3, c = i & 7;
            cpasync16(xh1a + (r * HPAD + 4 * c) * 4,
                      xg + (size_t)r * (GG * SS) + 32 + 4 * c);
        }
        CP_COMMIT();
    }

    // stage W1[g] transposed (regular stores, tiny) while x streams in
    {
        const float* W1g = W1 + (size_t)g * (SS * HH);
        for (int i = tid; i < SS * HH; i += ATH) {
            int s = i / HH, h = i - s * HH;
            wt[h * SS + s] = W1g[i];
        }
        if (tid < HH) {
            sb1[tid] = b1[g * HH + tid];
            sW2[tid] = W2[g * HH + tid];
        }
        if (tid == 0) sb2[0] = b2[g];
    }

    const bool v1 = (tid + 128) < nrows;
    const bool v2 = (tid + 256) < nrows;
    const int r1 = v1 ? (tid + 128) : 0;
    const int r2 = v2 ? (tid + 256) : 0;

    unsigned long long a0[HH], a1[HH], a2[HH];
#pragma unroll
    for (int h = 0; h < HH; h++) { a0[h] = 0ull; a1[h] = 0ull; a2[h] = 0ull; }

    // ---- half 0 ready (1 group still outstanding) ----
    CP_WAIT(1);
    __syncthreads();
#pragma unroll 4
    for (int q = 0; q < 8; q++) {
        ulonglong2 xa = *(const ulonglong2*)(xh0 + tid * HPAD + 4 * q);
        ulonglong2 xb = *(const ulonglong2*)(xh0 + r1  * HPAD + 4 * q);
        ulonglong2 xc = *(const ulonglong2*)(xh0 + r2  * HPAD + 4 * q);
#pragma unroll
        for (int h = 0; h < HH; h++) {
            ulonglong2 w = *(const ulonglong2*)(wt + h * SS + 4 * q);  // broadcast
            a0[h] = f2fma(xa.x, w.x, a0[h]);
            a1[h] = f2fma(xb.x, w.x, a1[h]);
            a2[h] = f2fma(xc.x, w.x, a2[h]);
            a0[h] = f2fma(xa.y, w.y, a0[h]);
            a1[h] = f2fma(xb.y, w.y, a1[h]);
            a2[h] = f2fma(xc.y, w.y, a2[h]);
        }
    }

    // ---- half 1 ----
    CP_WAIT(0);
    __syncthreads();
#pragma unroll 4
    for (int q = 0; q < 8; q++) {
        ulonglong2 xa = *(const ulonglong2*)(xh1 + tid * HPAD + 4 * q);
        ulonglong2 xb = *(const ulonglong2*)(xh1 + r1  * HPAD + 4 * q);
        ulonglong2 xc = *(const ulonglong2*)(xh1 + r2  * HPAD + 4 * q);
#pragma unroll
        for (int h = 0; h < HH; h++) {
            ulonglong2 w = *(const ulonglong2*)(wt + h * SS + 32 + 4 * q);
            a0[h] = f2fma(xa.x, w.x, a0[h]);
            a1[h] = f2fma(xb.x, w.x, a1[h]);
            a2[h] = f2fma(xc.x, w.x, a2[h]);
            a0[h] = f2fma(xa.y, w.y, a0[h]);
            a1[h] = f2fma(xb.y, w.y, a1[h]);
            a2[h] = f2fma(xc.y, w.y, a2[h]);
        }
    }

    // epilogue: relu + H->1 projection, coalesced store
    float o0 = sb2[0], o1 = sb2[0], o2 = sb2[0];
#pragma unroll
    for (int h = 0; h < HH; h++) {
        float w2h = sW2[h];
        float u0 = f2lo(a0[h]) + f2hi(a0[h]) + sb1[h];
        float u1 = f2lo(a1[h]) + f2hi(a1[h]) + sb1[h];
        float u2 = f2lo(a2[h]) + f2hi(a2[h]) + sb1[h];
        o0 = fmaf(fmaxf(u0, 0.f), w2h, o0);
        o1 = fmaf(fmaxf(u1, 0.f), w2h, o1);
        o2 = fmaf(fmaxf(u2, 0.f), w2h, o2);
    }
    float* glrow = g_glT + (size_t)g * BB + b0;
    glrow[tid] = o0;
    if (v1) glrow[tid + 128] = o1;
    if (v2) glrow[tid + 256] = o2;
}

// ---------------------------------------------------------------------------
// Kernel B: out[b] = relu(gl[b,:] @ Wp1 + bp1) @ Wp2 + bp2
// 256 blocks x 256 threads, 64 rows/block. gl read straight from L2-resident
// glT (no smem staging). Thread = rowslot(32; rows r,r+32) x jsub(8; 16 j).
// smem 67KB -> 2 blocks/SM.
// ---------------------------------------------------------------------------
#define B_THREADS 256
#define B_ROWSB 64
#define PHP 128
#define B_SMEM_FLOATS (GG * PHP + PHP + PHP + 8 * B_ROWSB)
#define B_SMEM_BYTES (B_SMEM_FLOATS * 4)

__global__ void __launch_bounds__(B_THREADS, 2)
kernelB(const float* __restrict__ Wp1, const float* __restrict__ bp1,
        const float* __restrict__ Wp2, const float* __restrict__ bp2,
        float* __restrict__ out) {
    float* sWp1 = (float*)dynsmem;            // [G][128] zero-padded
    float* sbp1 = sWp1 + GG * PHP;            // [128]
    float* sWp2 = sbp1 + PHP;                 // [128]
    float* op   = sWp2 + PHP;                 // [8][64] partials

    const int tid = threadIdx.x;
    const int b0 = blockIdx.x * B_ROWSB;

#pragma unroll 4
    for (int i = tid; i < GG * PHP; i += B_THREADS) {
        int g = i >> 7, j = i & (PHP - 1);
        sWp1[i] = (j < PHH) ? Wp1[g * PHH + j] : 0.f;
    }
    if (tid < PHP) {
        sbp1[tid] = (tid < PHH) ? bp1[tid] : 0.f;
        sWp2[tid] = (tid < PHH) ? Wp2[tid] : 0.f;
    }
    __syncthreads();

    const int row  = tid & 31;        // rows: row, row+32
    const int jsub = tid >> 5;        // warp-uniform: 8 subsets x 16 j
    const int jb   = jsub * 16;

    unsigned long long acc0[8], acc1[8];
#pragma unroll
    for (int c = 0; c < 8; c++) { acc0[c] = 0ull; acc1[c] = 0ull; }

    const float* glp = g_glT + b0 + row;
#pragma unroll 4
    for (int g = 0; g < GG; g++) {
        unsigned long long x0 = f2dup(__ldg(glp + (size_t)g * BB));
        unsigned long long x1 = f2dup(__ldg(glp + (size_t)g * BB + 32));
        const ulonglong2* wp = (const ulonglong2*)(sWp1 + g * PHP + jb);
#pragma unroll
        for (int p = 0; p < 4; p++) {
            ulonglong2 w = wp[p];
            acc0[2 * p]     = f2fma(x0, w.x, acc0[2 * p]);
            acc1[2 * p]     = f2fma(x1, w.x, acc1[2 * p]);
            acc0[2 * p + 1] = f2fma(x0, w.y, acc0[2 * p + 1]);
            acc1[2 * p + 1] = f2fma(x1, w.y, acc1[2 * p + 1]);
        }
    }

    float o0 = 0.f, o1 = 0.f;
#pragma unroll
    for (int c = 0; c < 8; c++) {
        int j0 = jb + 2 * c, j1 = j0 + 1;
        float p00 = fmaxf(f2lo(acc0[c]) + sbp1[j0], 0.f);
        float p01 = fmaxf(f2hi(acc0[c]) + sbp1[j1], 0.f);
        float p10 = fmaxf(f2lo(acc1[c]) + sbp1[j0], 0.f);
        float p11 = fmaxf(f2hi(acc1[c]) + sbp1[j1], 0.f);
        o0 = fmaf(p00, sWp2[j0], o0);
        o0 = fmaf(p01, sWp2[j1], o0);
        o1 = fmaf(p10, sWp2[j0], o1);
        o1 = fmaf(p11, sWp2[j1], o1);
    }
    op[jsub * B_ROWSB + row]      = o0;
    op[jsub * B_ROWSB + row + 32] = o1;
    __syncthreads();

    if (tid < B_ROWSB) {
        float v = bp2[0];
#pragma unroll
        for (int c = 0; c < 8; c++) v += op[c * B_ROWSB + tid];
        out[b0 + tid] = v;
    }
}

// ---------------------------------------------------------------------------
extern "C" void kernel_launch(void* const* d_in, const int* in_sizes, int n_in,
                              void* d_out, int out_size) {
    const float* x   = (const float*)d_in[0];
    const float* W1  = (const float*)d_in[1];
    const float* b1  = (const float*)d_in[2];
    const float* W2  = (const float*)d_in[3];
    const float* b2  = (const float*)d_in[4];
    const float* Wp1 = (const float*)d_in[5];
    const float* bp1 = (const float*)d_in[6];
    const float* Wp2 = (const float*)d_in[7];
    const float* bp2 = (const float*)d_in[8];
    float* out = (float*)d_out;

    cudaFuncSetAttribute(kernelA, cudaFuncAttributeMaxDynamicSharedMemorySize,
                         A_SMEM_BYTES);
    cudaFuncSetAttribute(kernelB, cudaFuncAttributeMaxDynamicSharedMemorySize,
                         B_SMEM_BYTES);

    // 3 slab launches (15 tiles each) so ncu's launch idx 5 captures kernelA
    dim3 gridA(GG, 15);
    kernelA<<<gridA, ATH, A_SMEM_BYTES>>>(x, W1, b1, W2, b2, 0);
    kernelA<<<gridA, ATH, A_SMEM_BYTES>>>(x, W1, b1, W2, b2, 15);
    kernelA<<<gridA, ATH, A_SMEM_BYTES>>>(x, W1, b1, W2, b2, 30);

    dim3 gridB(BB / B_ROWSB);
    kernelB<<<gridB, B_THREADS, B_SMEM_BYTES>>>(Wp1, bp1, Wp2, bp2, out);
}

// round 9
// speedup vs baseline: 1.6983x; 1.0893x over previous
#include <cuda_runtime.h>
#include <cstddef>
#include <cstdint>

#define BB 16384
#define GG 128
#define SS 64
#define HH 10
#define PHH 100

// 8MB scratch for gene_layer, stored TRANSPOSED: glT[g][b]
__device__ float g_glT[GG * BB];

// packed fp32x2 FMA (Blackwell; inline PTX only)
__device__ __forceinline__ unsigned long long f2fma(unsigned long long a,
                                                    unsigned long long b,
                                                    unsigned long long c) {
    unsigned long long d;
    asm("fma.rn.f32x2 %0, %1, %2, %3;" : "=l"(d) : "l"(a), "l"(b), "l"(c));
    return d;
}
__device__ __forceinline__ float f2lo(unsigned long long a) {
    return __uint_as_float((unsigned)a);
}
__device__ __forceinline__ float f2hi(unsigned long long a) {
    return __uint_as_float((unsigned)(a >> 32));
}
__device__ __forceinline__ unsigned long long f2dup(float v) {
    unsigned long long d;
    asm("mov.b64 %0, {%1, %1};" : "=l"(d) : "f"(v));
    return d;
}
__device__ __forceinline__ uint32_t smem_u32(const void* p) {
    uint32_t a;
    asm("{ .reg .u64 t; cvta.to.shared.u64 t, %1; cvt.u32.u64 %0, t; }"
        : "=r"(a) : "l"(p));
    return a;
}
__device__ __forceinline__ void cpasync16(uint32_t dst, const void* src) {
    asm volatile("cp.async.cg.shared.global [%0], [%1], 16;"
                 :: "r"(dst), "l"(src));
}
#define CP_COMMIT() asm volatile("cp.async.commit_group;" ::: "memory")
#define CP_WAIT(n)  asm volatile("cp.async.wait_group %0;" :: "n"(n) : "memory")

extern __shared__ unsigned char dynsmem[];

// ---------------------------------------------------------------------------
// Kernel A: gene_layer[b,g] = W2 . relu(x[b,g,:] @ W1[g] + b1) + b2
// Block = (gene, 512-row tile), 128 threads, R=4 rows/thread.
// s streamed in 4 chunks of 16 through 2 ping-pong cp.async buffers:
// fill(c+1) overlaps compute(c); accumulators persist. 2 blocks/SM.
// Crossbar/row ~= 2(STS) + 2(x) + 5(W/R=4) = 9 cyc.
// ---------------------------------------------------------------------------
#define AR 512        // rows per block; 16384/512 = 32 tiles, no tail
#define ATH 128
#define CPAD 20       // floats/row/chunk (16+4): 16B pitch; banks 20i mod 32 ok
#define NCHUNK 4      // s chunks of 16

#define A_SMEM_FLOATS (2 * AR * CPAD + HH * SS + 36)
#define A_SMEM_BYTES (A_SMEM_FLOATS * 4)

__device__ __forceinline__ void fill_chunk(uint32_t bufa, const float* xg,
                                           int chunk, int tid) {
    const float* src = xg + 16 * chunk;
#pragma unroll 4
    for (int i = tid; i < AR * 4; i += ATH) {
        int r = i >> 2, cc = i & 3;
        cpasync16(bufa + (r * CPAD + 4 * cc) * 4,
                  src + (size_t)r * (GG * SS) + 4 * cc);
    }
    CP_COMMIT();
}

__global__ void __launch_bounds__(ATH, 2)
kernelA(const float* __restrict__ x, const float* __restrict__ W1,
        const float* __restrict__ b1, const float* __restrict__ W2,
        const float* __restrict__ b2, int tile_off) {
    float* xb0 = (float*)dynsmem;        // [AR][CPAD] buffer 0
    float* xb1 = xb0 + AR * CPAD;        // [AR][CPAD] buffer 1
    float* wt  = xb1 + AR * CPAD;        // [HH][SS]  wt[h][s]
    float* sb1 = wt + HH * SS;           // [16]
    float* sW2 = sb1 + 16;               // [16]
    float* sb2 = sW2 + 16;               // [1]

    const int tid = threadIdx.x;
    const int g = blockIdx.x;
    const int b0 = (blockIdx.y + tile_off) * AR;

    const uint32_t ba[2] = { smem_u32(xb0), smem_u32(xb1) };
    float* const bp[2] = { xb0, xb1 };
    const float* xg = x + ((size_t)b0 * GG + g) * SS;

    // prime pipeline: chunks 0,1
    fill_chunk(ba[0], xg, 0, tid);
    fill_chunk(ba[1], xg, 1, tid);

    // stage W while x streams
    {
        const float* W1g = W1 + (size_t)g * (SS * HH);
        for (int i = tid; i < SS * HH; i += ATH) {
            int s = i / HH, h = i - s * HH;
            wt[h * SS + s] = W1g[i];
        }
        if (tid < HH) {
            sb1[tid] = b1[g * HH + tid];
            sW2[tid] = W2[g * HH + tid];
        }
        if (tid == 0) sb2[0] = b2[g];
    }

    unsigned long long a0[HH], a1[HH], a2[HH], a3[HH];
#pragma unroll
    for (int h = 0; h < HH; h++) { a0[h] = 0ull; a1[h] = 0ull; a2[h] = 0ull; a3[h] = 0ull; }

#pragma unroll 1
    for (int c = 0; c < NCHUNK; c++) {
        // wait for chunk c (pending after this: the one in-flight fill)
        if (c < NCHUNK - 1) { CP_WAIT(1); } else { CP_WAIT(0); }
        __syncthreads();

        const float* buf = bp[c & 1];
#pragma unroll
        for (int qq = 0; qq < 4; qq++) {
            int q = c * 4 + qq;   // global quad for W indexing
            ulonglong2 xa = *(const ulonglong2*)(buf + (tid)       * CPAD + 4 * qq);
            ulonglong2 xbv = *(const ulonglong2*)(buf + (tid + 128) * CPAD + 4 * qq);
            ulonglong2 xc = *(const ulonglong2*)(buf + (tid + 256) * CPAD + 4 * qq);
            ulonglong2 xd = *(const ulonglong2*)(buf + (tid + 384) * CPAD + 4 * qq);
#pragma unroll
            for (int h = 0; h < HH; h++) {
                ulonglong2 w = *(const ulonglong2*)(wt + h * SS + 4 * q); // bcast
                a0[h] = f2fma(xa.x,  w.x, a0[h]);
                a1[h] = f2fma(xbv.x, w.x, a1[h]);
                a2[h] = f2fma(xc.x,  w.x, a2[h]);
                a3[h] = f2fma(xd.x,  w.x, a3[h]);
                a0[h] = f2fma(xa.y,  w.y, a0[h]);
                a1[h] = f2fma(xbv.y, w.y, a1[h]);
                a2[h] = f2fma(xc.y,  w.y, a2[h]);
                a3[h] = f2fma(xd.y,  w.y, a3[h]);
            }
        }
        __syncthreads();   // all done reading buf before refill

        if (c + 2 < NCHUNK)
            fill_chunk(ba[c & 1], xg, c + 2, tid);
    }

    // epilogue: relu + H->1 projection, coalesced store
    float o0 = sb2[0], o1 = sb2[0], o2 = sb2[0], o3 = sb2[0];
#pragma unroll
    for (int h = 0; h < HH; h++) {
        float w2h = sW2[h];
        float u0 = f2lo(a0[h]) + f2hi(a0[h]) + sb1[h];
        float u1 = f2lo(a1[h]) + f2hi(a1[h]) + sb1[h];
        float u2 = f2lo(a2[h]) + f2hi(a2[h]) + sb1[h];
        float u3 = f2lo(a3[h]) + f2hi(a3[h]) + sb1[h];
        o0 = fmaf(fmaxf(u0, 0.f), w2h, o0);
        o1 = fmaf(fmaxf(u1, 0.f), w2h, o1);
        o2 = fmaf(fmaxf(u2, 0.f), w2h, o2);
        o3 = fmaf(fmaxf(u3, 0.f), w2h, o3);
    }
    float* glrow = g_glT + (size_t)g * BB + b0;
    glrow[tid]       = o0;
    glrow[tid + 128] = o1;
    glrow[tid + 256] = o2;
    glrow[tid + 384] = o3;
}

// ---------------------------------------------------------------------------
// Kernel B (reverted to R7 best: 25.3us): 128 blocks x 256 threads,
// 128 rows/block staged in smem. Thread = rowslot(32; 4 rows) x jsub(8; 16 j).
// ---------------------------------------------------------------------------
#define B_THREADS 256
#define B_ROWSB 128
#define PHP 128
#define B_SMEM_FLOATS (GG * B_ROWSB + GG * PHP + PHP + PHP + 8 * B_ROWSB)
#define B_SMEM_BYTES (B_SMEM_FLOATS * 4)

__global__ void __launch_bounds__(B_THREADS, 1)
kernelB(const float* __restrict__ Wp1, const float* __restrict__ bp1,
        const float* __restrict__ Wp2, const float* __restrict__ bp2,
        float* __restrict__ out) {
    float* gls  = (float*)dynsmem;            // [G][128] (g-major)
    float* sWp1 = gls + GG * B_ROWSB;         // [G][128] zero-padded
    float* sbp1 = sWp1 + GG * PHP;            // [128]
    float* sWp2 = sbp1 + PHP;                 // [128]
    float* op   = sWp2 + PHP;                 // [8][128] partials

    const int tid = threadIdx.x;
    const int b0 = blockIdx.x * B_ROWSB;

#pragma unroll 4
    for (int i = tid; i < GG * (B_ROWSB / 4); i += B_THREADS) {
        int k = i & 31, g = i >> 5;
        *(float4*)(gls + g * B_ROWSB + 4 * k) =
            *(const float4*)(g_glT + (size_t)g * BB + b0 + 4 * k);
    }
#pragma unroll 4
    for (int i = tid; i < GG * PHP; i += B_THREADS) {
        int g = i >> 7, j = i & (PHP - 1);
        sWp1[i] = (j < PHH) ? Wp1[g * PHH + j] : 0.f;
    }
    if (tid < PHP) {
        sbp1[tid] = (tid < PHH) ? bp1[tid] : 0.f;
        sWp2[tid] = (tid < PHH) ? Wp2[tid] : 0.f;
    }
    __syncthreads();

    const int row  = tid & 31;
    const int jsub = tid >> 5;
    const int jb   = jsub * 16;

    unsigned long long acc[4][8];
#pragma unroll
    for (int k = 0; k < 4; k++)
#pragma unroll
        for (int c = 0; c < 8; c++) acc[k][c] = 0ull;

#pragma unroll 2
    for (int g = 0; g < GG; g++) {
        const float* gr = gls + g * B_ROWSB + row;
        unsigned long long x0 = f2dup(gr[0]);
        unsigned long long x1 = f2dup(gr[32]);
        unsigned long long x2 = f2dup(gr[64]);
        unsigned long long x3 = f2dup(gr[96]);
        const ulonglong2* wp = (const ulonglong2*)(sWp1 + g * PHP + jb);
#pragma unroll
        for (int p = 0; p < 4; p++) {
            ulonglong2 w = wp[p];
            acc[0][2 * p]     = f2fma(x0, w.x, acc[0][2 * p]);
            acc[1][2 * p]     = f2fma(x1, w.x, acc[1][2 * p]);
            acc[2][2 * p]     = f2fma(x2, w.x, acc[2][2 * p]);
            acc[3][2 * p]     = f2fma(x3, w.x, acc[3][2 * p]);
            acc[0][2 * p + 1] = f2fma(x0, w.y, acc[0][2 * p + 1]);
            acc[1][2 * p + 1] = f2fma(x1, w.y, acc[1][2 * p + 1]);
            acc[2][2 * p + 1] = f2fma(x2, w.y, acc[2][2 * p + 1]);
            acc[3][2 * p + 1] = f2fma(x3, w.y, acc[3][2 * p + 1]);
        }
    }

#pragma unroll
    for (int k = 0; k < 4; k++) {
        float o = 0.f;
#pragma unroll
        for (int c = 0; c < 8; c++) {
            int j0 = jb + 2 * c, j1 = j0 + 1;
            float p0 = fmaxf(f2lo(acc[k][c]) + sbp1[j0], 0.f);
            float p1 = fmaxf(f2hi(acc[k][c]) + sbp1[j1], 0.f);
            o = fmaf(p0, sWp2[j0], o);
            o = fmaf(p1, sWp2[j1], o);
        }
        op[jsub * B_ROWSB + row + 32 * k] = o;
    }
    __syncthreads();

    if (tid < B_ROWSB) {
        float v = bp2[0];
#pragma unroll
        for (int c = 0; c < 8; c++) v += op[c * B_ROWSB + tid];
        out[b0 + tid] = v;
    }
}

// ---------------------------------------------------------------------------
extern "C" void kernel_launch(void* const* d_in, const int* in_sizes, int n_in,
                              void* d_out, int out_size) {
    const float* x   = (const float*)d_in[0];
    const float* W1  = (const float*)d_in[1];
    const float* b1  = (const float*)d_in[2];
    const float* W2  = (const float*)d_in[3];
    const float* b2  = (const float*)d_in[4];
    const float* Wp1 = (const float*)d_in[5];
    const float* bp1 = (const float*)d_in[6];
    const float* Wp2 = (const float*)d_in[7];
    const float* bp2 = (const float*)d_in[8];
    float* out = (float*)d_out;

    cudaFuncSetAttribute(kernelA, cudaFuncAttributeMaxDynamicSharedMemorySize,
                         A_SMEM_BYTES);
    cudaFuncSetAttribute(kernelB, cudaFuncAttributeMaxDynamicSharedMemorySize,
                         B_SMEM_BYTES);

    // 4 slab launches (8 tiles each): 5-launch period puts ncu idx 5 on kernelA
    dim3 gridA(GG, 8);
    kernelA<<<gridA, ATH, A_SMEM_BYTES>>>(x, W1, b1, W2, b2, 0);
    kernelA<<<gridA, ATH, A_SMEM_BYTES>>>(x, W1, b1, W2, b2, 8);
    kernelA<<<gridA, ATH, A_SMEM_BYTES>>>(x, W1, b1, W2, b2, 16);
    kernelA<<<gridA, ATH, A_SMEM_BYTES>>>(x, W1, b1, W2, b2, 24);

    dim3 gridB(BB / B_ROWSB);
    kernelB<<<gridB, B_THREADS, B_SMEM_BYTES>>>(Wp1, bp1, Wp2, bp2, out);
}